// round 2
// baseline (speedup 1.0000x reference)
#include <cuda_runtime.h>
#include <cuda_bf16.h>
#include <stdint.h>

#define B_ 4
#define S_ 2048
#define D_ 512
#define H_ 8
#define DK_ 64
#define MTOT_ (B_*S_)
#define YSZ_ (B_*S_*D_)

// ---------------- scratch (static device globals: the sanctioned workaround) ----
__device__ float g_Qh[B_*H_*S_*DK_];   // Q head-major, pre-scaled by 1/8
__device__ float g_Kh[B_*H_*S_*DK_];
__device__ float g_Vh[B_*H_*S_*DK_];
__device__ float g_ctx[MTOT_*D_];      // attention context, normalized
__device__ float g_x[MTOT_*D_];        // out-proj + residual (pre-LN)
__device__ float g_rs[B_*H_*S_];       // softmax row sums (unnormalized)

// ---------------- helpers ----------------
__device__ __forceinline__ uint32_t pack2(__nv_bfloat16 a, __nv_bfloat16 b){
  uint16_t ua = *reinterpret_cast<uint16_t*>(&a);
  uint16_t ub = *reinterpret_cast<uint16_t*>(&b);
  return (uint32_t)ua | ((uint32_t)ub << 16);
}
__device__ __forceinline__ void split2(float v, __nv_bfloat16& h, __nv_bfloat16& l){
  h = __float2bfloat16(v);
  l = __float2bfloat16(v - __bfloat162float(h));
}
__device__ __forceinline__ void mma_bf(float* c, uint32_t a0,uint32_t a1,uint32_t a2,uint32_t a3,
                                       uint32_t b0,uint32_t b1){
  asm volatile("mma.sync.aligned.m16n8k16.row.col.f32.bf16.bf16.f32 "
    "{%0,%1,%2,%3},{%4,%5,%6,%7},{%8,%9},{%0,%1,%2,%3};\n"
    : "+f"(c[0]),"+f"(c[1]),"+f"(c[2]),"+f"(c[3])
    : "r"(a0),"r"(a1),"r"(a2),"r"(a3),"r"(b0),"r"(b1));
}

// ---------------- GEMM core: one 128x128 tile of A[.,512] @ W[512,512] ----------
// Accumulates into acc[2][4][4] with split-bf16 (3 MMAs per k-step).
struct GemmCore {
  __device__ static void run(const float* __restrict__ A, const float* __restrict__ W,
                             int r0, int c0, float acc[2][4][4],
                             __nv_bfloat16* sA0, __nv_bfloat16* sA1,
                             __nv_bfloat16* sB0, __nv_bfloat16* sB1)
  {
    const int tid=threadIdx.x, warp=tid>>5, lane=tid&31;
    const int wr=warp>>2, wc=warp&3, g=lane>>2, t4=lane&3;
    for(int k0=0;k0<512;k0+=32){
      __syncthreads();
      #pragma unroll
      for(int j=0;j<8;j++){
        int i=tid+j*512; int rr=i>>5, kk=i&31;
        float v=A[(size_t)(r0+rr)*512 + k0+kk];
        __nv_bfloat16 hh,ll; split2(v,hh,ll);
        sA0[rr*40+kk]=hh; sA1[rr*40+kk]=ll;
      }
      #pragma unroll
      for(int j=0;j<8;j++){
        int i=tid+j*512; int nn=i&127, kk=i>>7;
        float v=W[(size_t)(k0+kk)*512 + c0+nn];
        __nv_bfloat16 hh,ll; split2(v,hh,ll);
        sB0[nn*40+kk]=hh; sB1[nn*40+kk]=ll;
      }
      __syncthreads();
      #pragma unroll
      for(int ks=0;ks<32;ks+=16){
        const int kc=ks+t4*2;
        uint32_t aH[2][4],aL[2][4],bH[4][2],bL[4][2];
        #pragma unroll
        for(int mi=0;mi<2;mi++){
          int r=wr*32+mi*16+g;
          aH[mi][0]=*(const uint32_t*)&sA0[r*40+kc];
          aH[mi][1]=*(const uint32_t*)&sA0[(r+8)*40+kc];
          aH[mi][2]=*(const uint32_t*)&sA0[r*40+kc+8];
          aH[mi][3]=*(const uint32_t*)&sA0[(r+8)*40+kc+8];
          aL[mi][0]=*(const uint32_t*)&sA1[r*40+kc];
          aL[mi][1]=*(const uint32_t*)&sA1[(r+8)*40+kc];
          aL[mi][2]=*(const uint32_t*)&sA1[r*40+kc+8];
          aL[mi][3]=*(const uint32_t*)&sA1[(r+8)*40+kc+8];
        }
        #pragma unroll
        for(int ni=0;ni<4;ni++){
          int n=wc*32+ni*8+g;
          bH[ni][0]=*(const uint32_t*)&sB0[n*40+kc];
          bH[ni][1]=*(const uint32_t*)&sB0[n*40+kc+8];
          bL[ni][0]=*(const uint32_t*)&sB1[n*40+kc];
          bL[ni][1]=*(const uint32_t*)&sB1[n*40+kc+8];
        }
        #pragma unroll
        for(int mi=0;mi<2;mi++)
          #pragma unroll
          for(int ni=0;ni<4;ni++){
            mma_bf(acc[mi][ni], aH[mi][0],aH[mi][1],aH[mi][2],aH[mi][3], bH[ni][0],bH[ni][1]);
            mma_bf(acc[mi][ni], aH[mi][0],aH[mi][1],aH[mi][2],aH[mi][3], bL[ni][0],bL[ni][1]);
            mma_bf(acc[mi][ni], aL[mi][0],aL[mi][1],aL[mi][2],aL[mi][3], bH[ni][0],bH[ni][1]);
          }
      }
    }
  }
};

// ---------------- K1: fused QKV projection (blockIdx.z selects Q/K/V) ----------
__global__ __launch_bounds__(512,1)
void qkv_gemm(const float* __restrict__ iQ, const float* __restrict__ iK,
              const float* __restrict__ iV, const float* __restrict__ WQ,
              const float* __restrict__ WK, const float* __restrict__ WV)
{
  __shared__ __nv_bfloat16 sA[2][128*40];
  __shared__ __nv_bfloat16 sB[2][128*40];
  const int tid=threadIdx.x, warp=tid>>5, lane=tid&31;
  const int wr=warp>>2, wc=warp&3, g=lane>>2, t4=lane&3;
  const int r0=blockIdx.y*128, c0=blockIdx.x*128;
  const int z=blockIdx.z;
  const float* A = (z==0)?iQ:(z==1)?iK:iV;
  const float* W = (z==0)?WQ:(z==1)?WK:WV;
  float* outp     = (z==0)?g_Qh:(z==1)?g_Kh:g_Vh;
  const float scale = (z==0)?0.125f:1.0f;

  float acc[2][4][4];
  #pragma unroll
  for(int mi=0;mi<2;mi++)
    #pragma unroll
    for(int ni=0;ni<4;ni++)
      #pragma unroll
      for(int e=0;e<4;e++) acc[mi][ni][e]=0.f;

  GemmCore::run(A,W,r0,c0,acc,sA[0],sA[1],sB[0],sB[1]);

  #pragma unroll
  for(int mi=0;mi<2;mi++)
   #pragma unroll
   for(int ni=0;ni<4;ni++)
    #pragma unroll
    for(int e=0;e<4;e++){
      int r=r0+wr*32+mi*16+g+((e>>1)<<3);
      int c=c0+wc*32+ni*8+t4*2+(e&1);
      float v=acc[mi][ni][e]*scale;
      int b=r>>11, s=r&2047, hh=c>>6, d=c&63;
      outp[((size_t)(b*H_+hh)*S_+s)*DK_ + d]=v;
    }
}

// ---------------- K4: out-proj + residual --------------------------------------
__global__ __launch_bounds__(512,1)
void out_gemm(const float* __restrict__ resid, const float* __restrict__ WO)
{
  __shared__ __nv_bfloat16 sA[2][128*40];
  __shared__ __nv_bfloat16 sB[2][128*40];
  const int tid=threadIdx.x, warp=tid>>5, lane=tid&31;
  const int wr=warp>>2, wc=warp&3, g=lane>>2, t4=lane&3;
  const int r0=blockIdx.y*128, c0=blockIdx.x*128;

  float acc[2][4][4];
  #pragma unroll
  for(int mi=0;mi<2;mi++)
    #pragma unroll
    for(int ni=0;ni<4;ni++)
      #pragma unroll
      for(int e=0;e<4;e++) acc[mi][ni][e]=0.f;

  GemmCore::run(g_ctx,WO,r0,c0,acc,sA[0],sA[1],sB[0],sB[1]);

  #pragma unroll
  for(int mi=0;mi<2;mi++)
   #pragma unroll
   for(int ni=0;ni<4;ni++)
    #pragma unroll
    for(int e=0;e<4;e++){
      int r=r0+wr*32+mi*16+g+((e>>1)<<3);
      int c=c0+wc*32+ni*8+t4*2+(e&1);
      g_x[(size_t)r*512+c]=acc[mi][ni][e] + resid[(size_t)r*512+c];
    }
}

// ---------------- K2: attention (per b,h,q-tile of 128) ------------------------
// Writes UNNORMALIZED exp(logits) to scores region, rowsums to g_rs,
// normalized context to g_ctx.
__global__ __launch_bounds__(512,1)
void attn_kernel(float* __restrict__ scores)
{
  extern __shared__ char smem_raw[];
  __nv_bfloat16* Qhi=(__nv_bfloat16*)smem_raw;      // 128 x 72
  __nv_bfloat16* Qlo=Qhi+128*72;
  __nv_bfloat16* Khi=Qlo+128*72;
  __nv_bfloat16* Klo=Khi+128*72;
  __nv_bfloat16* Vhi=Klo+128*72;                    // 64 x 136 (transposed)
  __nv_bfloat16* Vlo=Vhi+64*136;
  float* Psm=(float*)(Vlo+64*136);                  // 128 x 132 fp32
  float* rsm=Psm+128*132;                           // 128 rowsums

  const int tid=threadIdx.x, warp=tid>>5, lane=tid&31;
  const int wr=warp>>2, wc=warp&3, g=lane>>2, t4=lane&3;
  const int qt=blockIdx.x, h=blockIdx.y, b=blockIdx.z;
  const int bh=b*H_+h;
  const float* Qg=g_Qh+((size_t)bh*S_+qt*128)*DK_;
  const float* Kb=g_Kh+(size_t)bh*S_*DK_;
  const float* Vb=g_Vh+(size_t)bh*S_*DK_;
  float* scb=scores+((size_t)bh*S_+qt*128)*S_;

  #pragma unroll
  for(int j=0;j<16;j++){
    int i=tid+j*512; int r=i>>6,d=i&63;
    __nv_bfloat16 hh,ll; split2(Qg[i],hh,ll);
    Qhi[r*72+d]=hh; Qlo[r*72+d]=ll;
  }

  float cacc[2][2][4];
  #pragma unroll
  for(int mi=0;mi<2;mi++)
    #pragma unroll
    for(int ni=0;ni<2;ni++)
      #pragma unroll
      for(int e=0;e<4;e++) cacc[mi][ni][e]=0.f;
  float rs[8];
  #pragma unroll
  for(int rr=0;rr<8;rr++) rs[rr]=0.f;

  for(int kt=0;kt<16;kt++){
    __syncthreads();      // covers initial Q fill and Psm/V/K reuse
    const float* Kg=Kb+(size_t)kt*128*DK_;
    #pragma unroll
    for(int j=0;j<16;j++){
      int i=tid+j*512; int r=i>>6,d=i&63;
      __nv_bfloat16 hh,ll; split2(Kg[i],hh,ll);
      Khi[r*72+d]=hh; Klo[r*72+d]=ll;
    }
    __syncthreads();

    float sacc[2][4][4];
    #pragma unroll
    for(int mi=0;mi<2;mi++)
      #pragma unroll
      for(int ni=0;ni<4;ni++)
        #pragma unroll
        for(int e=0;e<4;e++) sacc[mi][ni][e]=0.f;

    #pragma unroll
    for(int ks=0;ks<64;ks+=16){
      const int kc=ks+t4*2;
      uint32_t aH[2][4],aL[2][4],bH[4][2],bL[4][2];
      #pragma unroll
      for(int mi=0;mi<2;mi++){
        int r=wr*32+mi*16+g;
        aH[mi][0]=*(const uint32_t*)&Qhi[r*72+kc];
        aH[mi][1]=*(const uint32_t*)&Qhi[(r+8)*72+kc];
        aH[mi][2]=*(const uint32_t*)&Qhi[r*72+kc+8];
        aH[mi][3]=*(const uint32_t*)&Qhi[(r+8)*72+kc+8];
        aL[mi][0]=*(const uint32_t*)&Qlo[r*72+kc];
        aL[mi][1]=*(const uint32_t*)&Qlo[(r+8)*72+kc];
        aL[mi][2]=*(const uint32_t*)&Qlo[r*72+kc+8];
        aL[mi][3]=*(const uint32_t*)&Qlo[(r+8)*72+kc+8];
      }
      #pragma unroll
      for(int ni=0;ni<4;ni++){
        int n=wc*32+ni*8+g;
        bH[ni][0]=*(const uint32_t*)&Khi[n*72+kc];
        bH[ni][1]=*(const uint32_t*)&Khi[n*72+kc+8];
        bL[ni][0]=*(const uint32_t*)&Klo[n*72+kc];
        bL[ni][1]=*(const uint32_t*)&Klo[n*72+kc+8];
      }
      #pragma unroll
      for(int mi=0;mi<2;mi++)
        #pragma unroll
        for(int ni=0;ni<4;ni++){
          mma_bf(sacc[mi][ni], aH[mi][0],aH[mi][1],aH[mi][2],aH[mi][3], bH[ni][0],bH[ni][1]);
          mma_bf(sacc[mi][ni], aH[mi][0],aH[mi][1],aH[mi][2],aH[mi][3], bL[ni][0],bL[ni][1]);
          mma_bf(sacc[mi][ni], aL[mi][0],aL[mi][1],aL[mi][2],aL[mi][3], bH[ni][0],bH[ni][1]);
        }
    }

    // exp (logits already scaled by 1/8 via Q) -> Psm
    #pragma unroll
    for(int mi=0;mi<2;mi++)
     #pragma unroll
     for(int ni=0;ni<4;ni++)
      #pragma unroll
      for(int e=0;e<4;e++){
        int r=wr*32+mi*16+g+((e>>1)<<3);
        int c=wc*32+ni*8+t4*2+(e&1);
        Psm[r*132+c]=__expf(sacc[mi][ni][e]);
      }

    // V tile, transposed into [feat][key]
    const float* Vg=Vb+(size_t)kt*128*DK_;
    #pragma unroll
    for(int j=0;j<16;j++){
      int i=tid+j*512; int key=i>>6,d=i&63;
      __nv_bfloat16 hh,ll; split2(Vg[i],hh,ll);
      Vhi[d*136+key]=hh; Vlo[d*136+key]=ll;
    }
    __syncthreads();

    // coalesced scores store + rowsum accumulation (warp owns 8 rows)
    #pragma unroll
    for(int rr=0;rr<8;rr++){
      int row=warp*8+rr;
      float4 v=*(const float4*)&Psm[row*132+lane*4];
      *(float4*)&scb[(size_t)row*S_+kt*128+lane*4]=v;
      rs[rr]+=v.x+v.y+v.z+v.w;
    }

    // PV: context += P @ V  (split-bf16, P split on the fly)
    #pragma unroll
    for(int ks=0;ks<128;ks+=16){
      const int kc=ks+t4*2;
      uint32_t aH[2][4],aL[2][4];
      #pragma unroll
      for(int mi=0;mi<2;mi++){
        int r=wr*32+mi*16+g;
        float2 p0=*(const float2*)&Psm[r*132+kc];
        float2 p1=*(const float2*)&Psm[(r+8)*132+kc];
        float2 p2=*(const float2*)&Psm[r*132+kc+8];
        float2 p3=*(const float2*)&Psm[(r+8)*132+kc+8];
        __nv_bfloat16 h0,l0,h1,l1;
        split2(p0.x,h0,l0); split2(p0.y,h1,l1);
        aH[mi][0]=pack2(h0,h1); aL[mi][0]=pack2(l0,l1);
        split2(p1.x,h0,l0); split2(p1.y,h1,l1);
        aH[mi][1]=pack2(h0,h1); aL[mi][1]=pack2(l0,l1);
        split2(p2.x,h0,l0); split2(p2.y,h1,l1);
        aH[mi][2]=pack2(h0,h1); aL[mi][2]=pack2(l0,l1);
        split2(p3.x,h0,l0); split2(p3.y,h1,l1);
        aH[mi][3]=pack2(h0,h1); aL[mi][3]=pack2(l0,l1);
      }
      uint32_t bH[2][2],bL[2][2];
      #pragma unroll
      for(int ni=0;ni<2;ni++){
        int n=wc*16+ni*8+g;
        bH[ni][0]=*(const uint32_t*)&Vhi[n*136+kc];
        bH[ni][1]=*(const uint32_t*)&Vhi[n*136+kc+8];
        bL[ni][0]=*(const uint32_t*)&Vlo[n*136+kc];
        bL[ni][1]=*(const uint32_t*)&Vlo[n*136+kc+8];
      }
      #pragma unroll
      for(int mi=0;mi<2;mi++)
        #pragma unroll
        for(int ni=0;ni<2;ni++){
          mma_bf(cacc[mi][ni], aH[mi][0],aH[mi][1],aH[mi][2],aH[mi][3], bH[ni][0],bH[ni][1]);
          mma_bf(cacc[mi][ni], aH[mi][0],aH[mi][1],aH[mi][2],aH[mi][3], bL[ni][0],bL[ni][1]);
          mma_bf(cacc[mi][ni], aL[mi][0],aL[mi][1],aL[mi][2],aL[mi][3], bH[ni][0],bH[ni][1]);
        }
    }
  }

  // row sums: warp-level reduce (each warp owns rows warp*8..+7)
  #pragma unroll
  for(int rr=0;rr<8;rr++){
    float v=rs[rr];
    #pragma unroll
    for(int o=16;o;o>>=1) v+=__shfl_xor_sync(0xffffffffu,v,o);
    if(lane==0){
      rsm[warp*8+rr]=v;
      g_rs[(size_t)bh*S_+qt*128+warp*8+rr]=v;
    }
  }
  __syncthreads();

  // normalized context -> g_ctx [b,s,h*64+d]
  float* ctx=g_ctx+((size_t)(b*S_+qt*128))*D_ + h*DK_;
  #pragma unroll
  for(int mi=0;mi<2;mi++)
   #pragma unroll
   for(int ni=0;ni<2;ni++)
    #pragma unroll
    for(int e=0;e<4;e++){
      int r=wr*32+mi*16+g+((e>>1)<<3);
      int c=wc*16+ni*8+t4*2+(e&1);
      ctx[(size_t)r*D_+c]=cacc[mi][ni][e]/rsm[r];
    }
}

// ---------------- K3: normalize scores rows ------------------------------------
__global__ __launch_bounds__(256)
void norm_scores(float* __restrict__ scores)
{
  size_t row=blockIdx.x;
  float inv=1.0f/g_rs[row];
  float4* p=(float4*)(scores+row*(size_t)S_);
  int i=threadIdx.x;
  float4 v=p[i];
  v.x*=inv; v.y*=inv; v.z*=inv; v.w*=inv;
  p[i]=v;
  float4 w=p[i+256];
  w.x*=inv; w.y*=inv; w.z*=inv; w.w*=inv;
  p[i+256]=w;
}

// ---------------- K5: LayerNorm ------------------------------------------------
__global__ __launch_bounds__(128)
void ln_kernel(const float* __restrict__ gamma, const float* __restrict__ beta,
               float* __restrict__ y)
{
  int row=blockIdx.x, tid=threadIdx.x;
  int warp=tid>>5, lane=tid&31;
  const float4 v=*(const float4*)(g_x+(size_t)row*512+tid*4);
  float s=v.x+v.y+v.z+v.w;
  #pragma unroll
  for(int o=16;o;o>>=1) s+=__shfl_xor_sync(0xffffffffu,s,o);
  __shared__ float red[4];
  if(lane==0) red[warp]=s;
  __syncthreads();
  float mean=(red[0]+red[1]+red[2]+red[3])*(1.0f/512.0f);
  float d0=v.x-mean, d1=v.y-mean, d2=v.z-mean, d3=v.w-mean;
  float q=d0*d0+d1*d1+d2*d2+d3*d3;
  #pragma unroll
  for(int o=16;o;o>>=1) q+=__shfl_xor_sync(0xffffffffu,q,o);
  __syncthreads();
  if(lane==0) red[warp]=q;
  __syncthreads();
  float var=(red[0]+red[1]+red[2]+red[3])*(1.0f/512.0f);
  float rstd=rsqrtf(var+1e-5f);
  const float4 gm=*(const float4*)(gamma+tid*4);
  const float4 bt=*(const float4*)(beta+tid*4);
  float4 o;
  o.x=d0*rstd*gm.x+bt.x;
  o.y=d1*rstd*gm.y+bt.y;
  o.z=d2*rstd*gm.z+bt.z;
  o.w=d3*rstd*gm.w+bt.w;
  *(float4*)(y+(size_t)row*512+tid*4)=o;
}

// ---------------- launch -------------------------------------------------------
extern "C" void kernel_launch(void* const* d_in, const int* in_sizes, int n_in,
                              void* d_out, int out_size)
{
  (void)in_sizes; (void)n_in; (void)out_size;
  const float* iQ=(const float*)d_in[0];
  const float* iK=(const float*)d_in[1];
  const float* iV=(const float*)d_in[2];
  const float* WQ=(const float*)d_in[3];
  const float* WK=(const float*)d_in[4];
  const float* WV=(const float*)d_in[5];
  const float* WO=(const float*)d_in[6];
  const float* gamma=(const float*)d_in[7];
  const float* beta =(const float*)d_in[8];
  float* out=(float*)d_out;
  float* y=out;
  float* scores=out+YSZ_;

  const int ATTN_SMEM = 4*(128*72)*2 + 2*(64*136)*2 + 128*132*4 + 128*4; // 176640
  static bool attr_done=false;
  if(!attr_done){
    cudaFuncSetAttribute(attn_kernel, cudaFuncAttributeMaxDynamicSharedMemorySize, ATTN_SMEM);
    attr_done=true;
  }

  qkv_gemm<<<dim3(4,64,3),512>>>(iQ,iK,iV,WQ,WK,WV);

  attn_kernel<<<dim3(16,8,4),512,ATTN_SMEM>>>(scores);

  norm_scores<<<B_*H_*S_,256>>>(scores);

  out_gemm<<<dim3(4,64,1),512>>>(iQ,WO);

  ln_kernel<<<MTOT_,128>>>(gamma,beta,y);
}

// round 5
// speedup vs baseline: 1.2908x; 1.2908x over previous
#include <cuda_runtime.h>
#include <cuda_bf16.h>
#include <stdint.h>

#define B_ 4
#define S_ 2048
#define D_ 512
#define H_ 8
#define DK_ 64
#define MTOT_ (B_*S_)
#define YSZ_ (B_*S_*D_)

// ---------------- scratch ----------------
__device__ __nv_bfloat16 g_inhi[3*MTOT_*D_], g_inlo[3*MTOT_*D_];   // split inputs
__device__ __nv_bfloat16 g_whi[4*D_*D_],     g_wlo[4*D_*D_];       // split weights
__device__ __nv_bfloat16 g_Qhi[B_*H_*S_*DK_], g_Qlo[B_*H_*S_*DK_]; // head-major, Q pre-scaled 1/8
__device__ __nv_bfloat16 g_Khi[B_*H_*S_*DK_], g_Klo[B_*H_*S_*DK_];
__device__ __nv_bfloat16 g_Vhi[B_*H_*S_*DK_], g_Vlo[B_*H_*S_*DK_];
__device__ __nv_bfloat16 g_chi[MTOT_*D_],     g_clo[MTOT_*D_];     // ctx hi/lo
__device__ float g_x[MTOT_*D_];    // out-proj + residual (pre-LN)
__device__ float g_rs[B_*H_*S_];   // softmax row sums (unnormalized)

// ---------------- helpers ----------------
__device__ __forceinline__ uint32_t s2u(const void* p){
  return (uint32_t)__cvta_generic_to_shared(p);
}
__device__ __forceinline__ void split2(float v, __nv_bfloat16& h, __nv_bfloat16& l){
  h = __float2bfloat16(v);
  l = __float2bfloat16(v - __bfloat162float(h));
}
__device__ __forceinline__ void mma_bf(float* c, uint32_t a0,uint32_t a1,uint32_t a2,uint32_t a3,
                                       uint32_t b0,uint32_t b1){
  asm volatile("mma.sync.aligned.m16n8k16.row.col.f32.bf16.bf16.f32 "
    "{%0,%1,%2,%3},{%4,%5,%6,%7},{%8,%9},{%0,%1,%2,%3};\n"
    : "+f"(c[0]),"+f"(c[1]),"+f"(c[2]),"+f"(c[3])
    : "r"(a0),"r"(a1),"r"(a2),"r"(a3),"r"(b0),"r"(b1));
}
#define LDSM4(R0,R1,R2,R3,ADDR) \
  asm volatile("ldmatrix.sync.aligned.m8n8.x4.shared.b16 {%0,%1,%2,%3},[%4];\n" \
    :"=r"(R0),"=r"(R1),"=r"(R2),"=r"(R3):"r"(ADDR))
#define LDSM4T(R0,R1,R2,R3,ADDR) \
  asm volatile("ldmatrix.sync.aligned.m8n8.x4.trans.shared.b16 {%0,%1,%2,%3},[%4];\n" \
    :"=r"(R0),"=r"(R1),"=r"(R2),"=r"(R3):"r"(ADDR))

// ---------------- prep: split fp32 -> bf16 hi/lo -------------------------------
__global__ __launch_bounds__(256)
void split_in(const float* __restrict__ s0, const float* __restrict__ s1,
              const float* __restrict__ s2)
{
  const int z=blockIdx.z;
  const float* src = (z==0)?s0:(z==1)?s1:s2;
  size_t off=(size_t)z*MTOT_*D_;
  size_t i=((size_t)blockIdx.x*256+threadIdx.x)*4;
  float4 v=*(const float4*)(src+i);
  __nv_bfloat16 h0,l0,h1,l1,h2,l2,h3,l3;
  split2(v.x,h0,l0); split2(v.y,h1,l1); split2(v.z,h2,l2); split2(v.w,h3,l3);
  *(__nv_bfloat162*)(g_inhi+off+i)  =__halves2bfloat162(h0,h1);
  *(__nv_bfloat162*)(g_inhi+off+i+2)=__halves2bfloat162(h2,h3);
  *(__nv_bfloat162*)(g_inlo+off+i)  =__halves2bfloat162(l0,l1);
  *(__nv_bfloat162*)(g_inlo+off+i+2)=__halves2bfloat162(l2,l3);
}
__global__ __launch_bounds__(256)
void split_w(const float* __restrict__ w0, const float* __restrict__ w1,
             const float* __restrict__ w2, const float* __restrict__ w3)
{
  const int z=blockIdx.z;
  const float* src = (z==0)?w0:(z==1)?w1:(z==2)?w2:w3;
  size_t off=(size_t)z*D_*D_;
  size_t i=((size_t)blockIdx.x*256+threadIdx.x)*4;
  float4 v=*(const float4*)(src+i);
  __nv_bfloat16 h0,l0,h1,l1,h2,l2,h3,l3;
  split2(v.x,h0,l0); split2(v.y,h1,l1); split2(v.z,h2,l2); split2(v.w,h3,l3);
  *(__nv_bfloat162*)(g_whi+off+i)  =__halves2bfloat162(h0,h1);
  *(__nv_bfloat162*)(g_whi+off+i+2)=__halves2bfloat162(h2,h3);
  *(__nv_bfloat162*)(g_wlo+off+i)  =__halves2bfloat162(l0,l1);
  *(__nv_bfloat162*)(g_wlo+off+i+2)=__halves2bfloat162(l2,l3);
}

// ---------------- GEMM core: 128x128 tile of A[.,512] @ W[512,512] -------------
// A hi/lo: [M][512] bf16 row-major.  W hi/lo: [512][512] bf16 row-major ([k][n]).
// smem: sAh/sAl [128][72], sWh/sWl [64][136]. k-tile = 64.
__device__ __forceinline__ void gemm_core(
    const __nv_bfloat16* __restrict__ Ahi, const __nv_bfloat16* __restrict__ Alo,
    const __nv_bfloat16* __restrict__ Whi, const __nv_bfloat16* __restrict__ Wlo,
    int r0, int c0, float acc[2][4][4], char* sm)
{
  __nv_bfloat16* sAh=(__nv_bfloat16*)sm;
  __nv_bfloat16* sAl=sAh+128*72;
  __nv_bfloat16* sWh=sAl+128*72;   // [64][136]
  __nv_bfloat16* sWl=sWh+64*136;
  const int tid=threadIdx.x, warp=tid>>5, lane=tid&31;
  const int wr=warp>>2, wc=warp&3;
  const int r16=lane&15, c2=lane>>4;

  uint32_t aAh[2],aAl[2],bWh[2],bWl[2];
  #pragma unroll
  for(int mi=0;mi<2;mi++){
    int row=wr*32+mi*16+r16;
    aAh[mi]=s2u(sAh)+(uint32_t)(row*72+c2*8)*2;
    aAl[mi]=s2u(sAl)+(uint32_t)(row*72+c2*8)*2;
  }
  #pragma unroll
  for(int j=0;j<2;j++){
    int col=wc*32+j*16+c2*8;
    bWh[j]=s2u(sWh)+(uint32_t)(r16*136+col)*2;
    bWl[j]=s2u(sWl)+(uint32_t)(r16*136+col)*2;
  }

  for(int k0=0;k0<512;k0+=64){
    __syncthreads();
    #pragma unroll
    for(int j=0;j<2;j++){
      int v=tid+j*512; int r=v>>3, kb=(v&7)*8;
      *(uint4*)(sAh+r*72+kb)=*(const uint4*)(Ahi+(size_t)(r0+r)*512+k0+kb);
      *(uint4*)(sAl+r*72+kb)=*(const uint4*)(Alo+(size_t)(r0+r)*512+k0+kb);
    }
    #pragma unroll
    for(int j=0;j<2;j++){
      int v=tid+j*512; int kk=v>>4, cb=(v&15)*8;
      *(uint4*)(sWh+kk*136+cb)=*(const uint4*)(Whi+(size_t)(k0+kk)*512+c0+cb);
      *(uint4*)(sWl+kk*136+cb)=*(const uint4*)(Wlo+(size_t)(k0+kk)*512+c0+cb);
    }
    __syncthreads();
    #pragma unroll
    for(int ks=0;ks<64;ks+=16){
      uint32_t aH[2][4],aL[2][4],bH[4][2],bL[4][2];
      #pragma unroll
      for(int mi=0;mi<2;mi++){
        LDSM4(aH[mi][0],aH[mi][1],aH[mi][2],aH[mi][3], aAh[mi]+ks*2);
        LDSM4(aL[mi][0],aL[mi][1],aL[mi][2],aL[mi][3], aAl[mi]+ks*2);
      }
      #pragma unroll
      for(int j=0;j<2;j++){
        LDSM4T(bH[2*j][0],bH[2*j][1],bH[2*j+1][0],bH[2*j+1][1], bWh[j]+ks*272);
        LDSM4T(bL[2*j][0],bL[2*j][1],bL[2*j+1][0],bL[2*j+1][1], bWl[j]+ks*272);
      }
      #pragma unroll
      for(int mi=0;mi<2;mi++)
        #pragma unroll
        for(int ni=0;ni<4;ni++){
          mma_bf(acc[mi][ni], aH[mi][0],aH[mi][1],aH[mi][2],aH[mi][3], bH[ni][0],bH[ni][1]);
          mma_bf(acc[mi][ni], aH[mi][0],aH[mi][1],aH[mi][2],aH[mi][3], bL[ni][0],bL[ni][1]);
          mma_bf(acc[mi][ni], aL[mi][0],aL[mi][1],aL[mi][2],aL[mi][3], bH[ni][0],bH[ni][1]);
        }
    }
  }
}

#define GEMM_SMEM (2*(128*72)*2 + 2*(64*136)*2)

// ---------------- K1: fused QKV projection (blockIdx.z selects Q/K/V) ----------
__global__ __launch_bounds__(512,1)
void qkv_gemm()
{
  extern __shared__ char sm[];
  const int tid=threadIdx.x, warp=tid>>5, lane=tid&31;
  const int wr=warp>>2, wc=warp&3, g=lane>>2, t4=lane&3;
  const int r0=blockIdx.y*128, c0=blockIdx.x*128;
  const int z=blockIdx.z;
  const __nv_bfloat16* Ahi=g_inhi+(size_t)z*MTOT_*D_;
  const __nv_bfloat16* Alo=g_inlo+(size_t)z*MTOT_*D_;
  const __nv_bfloat16* Whi=g_whi+(size_t)z*D_*D_;
  const __nv_bfloat16* Wlo=g_wlo+(size_t)z*D_*D_;
  __nv_bfloat16* outhi=(z==0)?g_Qhi:(z==1)?g_Khi:g_Vhi;
  __nv_bfloat16* outlo=(z==0)?g_Qlo:(z==1)?g_Klo:g_Vlo;
  const float scale=(z==0)?0.125f:1.0f;

  float acc[2][4][4];
  #pragma unroll
  for(int mi=0;mi<2;mi++)
    #pragma unroll
    for(int ni=0;ni<4;ni++)
      #pragma unroll
      for(int e=0;e<4;e++) acc[mi][ni][e]=0.f;

  gemm_core(Ahi,Alo,Whi,Wlo,r0,c0,acc,sm);

  #pragma unroll
  for(int mi=0;mi<2;mi++)
   #pragma unroll
   for(int ni=0;ni<4;ni++)
    #pragma unroll
    for(int e=0;e<4;e++){
      int r=r0+wr*32+mi*16+g+((e>>1)<<3);
      int c=c0+wc*32+ni*8+t4*2+(e&1);
      float v=acc[mi][ni][e]*scale;
      int b=r>>11, s=r&2047, hh=c>>6, d=c&63;
      size_t idx=((size_t)(b*H_+hh)*S_+s)*DK_+d;
      __nv_bfloat16 vh,vl; split2(v,vh,vl);
      outhi[idx]=vh; outlo[idx]=vl;
    }
}

// ---------------- K4: out-proj + residual --------------------------------------
__global__ __launch_bounds__(512,1)
void out_gemm(const float* __restrict__ resid)
{
  extern __shared__ char sm[];
  const int tid=threadIdx.x, warp=tid>>5, lane=tid&31;
  const int wr=warp>>2, wc=warp&3, g=lane>>2, t4=lane&3;
  const int r0=blockIdx.y*128, c0=blockIdx.x*128;

  float acc[2][4][4];
  #pragma unroll
  for(int mi=0;mi<2;mi++)
    #pragma unroll
    for(int ni=0;ni<4;ni++)
      #pragma unroll
      for(int e=0;e<4;e++) acc[mi][ni][e]=0.f;

  gemm_core(g_chi,g_clo,g_whi+(size_t)3*D_*D_,g_wlo+(size_t)3*D_*D_,r0,c0,acc,sm);

  #pragma unroll
  for(int mi=0;mi<2;mi++)
   #pragma unroll
   for(int ni=0;ni<4;ni++)
    #pragma unroll
    for(int e=0;e<4;e++){
      int r=r0+wr*32+mi*16+g+((e>>1)<<3);
      int c=c0+wc*32+ni*8+t4*2+(e&1);
      g_x[(size_t)r*512+c]=acc[mi][ni][e]+resid[(size_t)r*512+c];
    }
}

// ---------------- K2: attention (per b,h,q-tile of 128) ------------------------
__global__ __launch_bounds__(512,1)
void attn_kernel(float* __restrict__ scores)
{
  extern __shared__ char sm[];
  __nv_bfloat16* Qh=(__nv_bfloat16*)sm;   // [128][72]
  __nv_bfloat16* Ql=Qh+128*72;
  __nv_bfloat16* Kh=Ql+128*72;            // [key][d] [128][72]
  __nv_bfloat16* Kl=Kh+128*72;
  __nv_bfloat16* Vh=Kl+128*72;            // [key][d] [128][72]
  __nv_bfloat16* Vl=Vh+128*72;
  __nv_bfloat16* Ph=Vl+128*72;            // [128][136]
  __nv_bfloat16* Pl=Ph+128*136;
  float* rsm=(float*)(Pl+128*136);        // 128

  const int tid=threadIdx.x, warp=tid>>5, lane=tid&31;
  const int wr=warp>>2, wc=warp&3, g=lane>>2, t4=lane&3;
  const int r16=lane&15, c2=lane>>4;
  const int nbrow=(lane&7)+(lane>>4)*8, nbc=(lane>>3)&1;
  const int qt=blockIdx.x, h=blockIdx.y, b=blockIdx.z;
  const int bh=b*H_+h;
  const __nv_bfloat16* Qghi=g_Qhi+((size_t)bh*S_+qt*128)*DK_;
  const __nv_bfloat16* Qglo=g_Qlo+((size_t)bh*S_+qt*128)*DK_;
  const __nv_bfloat16* Kbhi=g_Khi+(size_t)bh*S_*DK_;
  const __nv_bfloat16* Kblo=g_Klo+(size_t)bh*S_*DK_;
  const __nv_bfloat16* Vbhi=g_Vhi+(size_t)bh*S_*DK_;
  const __nv_bfloat16* Vblo=g_Vlo+(size_t)bh*S_*DK_;
  float* scb=scores+((size_t)bh*S_+qt*128)*S_;

  // Q tile -> smem (vectorized)
  #pragma unroll
  for(int j=0;j<2;j++){
    int v=tid+j*512; int r=v>>3, db=(v&7)*8;
    *(uint4*)(Qh+r*72+db)=*(const uint4*)(Qghi+r*64+db);
    *(uint4*)(Ql+r*72+db)=*(const uint4*)(Qglo+r*64+db);
  }

  // fragment addresses
  uint32_t aQh[2],aQl[2],aPh[2],aPl[2];
  #pragma unroll
  for(int mi=0;mi<2;mi++){
    int row=wr*32+mi*16+r16;
    aQh[mi]=s2u(Qh)+(uint32_t)(row*72+c2*8)*2;
    aQl[mi]=s2u(Ql)+(uint32_t)(row*72+c2*8)*2;
    aPh[mi]=s2u(Ph)+(uint32_t)(row*136+c2*8)*2;
    aPl[mi]=s2u(Pl)+(uint32_t)(row*136+c2*8)*2;
  }
  uint32_t bKh[2],bKl[2];
  #pragma unroll
  for(int j=0;j<2;j++){
    int row=wc*32+j*16+nbrow;
    bKh[j]=s2u(Kh)+(uint32_t)(row*72+nbc*8)*2;
    bKl[j]=s2u(Kl)+(uint32_t)(row*72+nbc*8)*2;
  }
  uint32_t bVh=s2u(Vh)+(uint32_t)(r16*72+wc*16+c2*8)*2;
  uint32_t bVl=s2u(Vl)+(uint32_t)(r16*72+wc*16+c2*8)*2;

  float cacc[2][2][4];
  #pragma unroll
  for(int mi=0;mi<2;mi++)
    #pragma unroll
    for(int ni=0;ni<2;ni++)
      #pragma unroll
      for(int e=0;e<4;e++) cacc[mi][ni][e]=0.f;
  float rs[8];
  #pragma unroll
  for(int rr=0;rr<8;rr++) rs[rr]=0.f;

  for(int kt=0;kt<16;kt++){
    __syncthreads();                        // prev PV / scores done
    const __nv_bfloat16* Kghi=Kbhi+(size_t)kt*128*DK_;
    const __nv_bfloat16* Kglo=Kblo+(size_t)kt*128*DK_;
    #pragma unroll
    for(int j=0;j<2;j++){
      int v=tid+j*512; int r=v>>3, db=(v&7)*8;
      *(uint4*)(Kh+r*72+db)=*(const uint4*)(Kghi+r*64+db);
      *(uint4*)(Kl+r*72+db)=*(const uint4*)(Kglo+r*64+db);
    }
    __syncthreads();

    float sacc[2][4][4];
    #pragma unroll
    for(int mi=0;mi<2;mi++)
      #pragma unroll
      for(int ni=0;ni<4;ni++)
        #pragma unroll
        for(int e=0;e<4;e++) sacc[mi][ni][e]=0.f;

    #pragma unroll
    for(int ks=0;ks<64;ks+=16){
      uint32_t aH[2][4],aL[2][4],bH[4][2],bL[4][2];
      #pragma unroll
      for(int mi=0;mi<2;mi++){
        LDSM4(aH[mi][0],aH[mi][1],aH[mi][2],aH[mi][3], aQh[mi]+ks*2);
        LDSM4(aL[mi][0],aL[mi][1],aL[mi][2],aL[mi][3], aQl[mi]+ks*2);
      }
      #pragma unroll
      for(int j=0;j<2;j++){
        LDSM4(bH[2*j][0],bH[2*j][1],bH[2*j+1][0],bH[2*j+1][1], bKh[j]+ks*2);
        LDSM4(bL[2*j][0],bL[2*j][1],bL[2*j+1][0],bL[2*j+1][1], bKl[j]+ks*2);
      }
      #pragma unroll
      for(int mi=0;mi<2;mi++)
        #pragma unroll
        for(int ni=0;ni<4;ni++){
          mma_bf(sacc[mi][ni], aH[mi][0],aH[mi][1],aH[mi][2],aH[mi][3], bH[ni][0],bH[ni][1]);
          mma_bf(sacc[mi][ni], aH[mi][0],aH[mi][1],aH[mi][2],aH[mi][3], bL[ni][0],bL[ni][1]);
          mma_bf(sacc[mi][ni], aL[mi][0],aL[mi][1],aL[mi][2],aL[mi][3], bH[ni][0],bH[ni][1]);
        }
    }

    // exp -> P hi/lo (bf16, mma layout)
    #pragma unroll
    for(int mi=0;mi<2;mi++)
     #pragma unroll
     for(int ni=0;ni<4;ni++)
      #pragma unroll
      for(int e=0;e<4;e++){
        int r=wr*32+mi*16+g+((e>>1)<<3);
        int c=wc*32+ni*8+t4*2+(e&1);
        float p=__expf(sacc[mi][ni][e]);
        __nv_bfloat16 ph,pl; split2(p,ph,pl);
        Ph[r*136+c]=ph; Pl[r*136+c]=pl;
      }

    // V tile -> smem (natural [key][d] layout; trans-ldmatrix consumes it)
    const __nv_bfloat16* Vghi=Vbhi+(size_t)kt*128*DK_;
    const __nv_bfloat16* Vglo=Vblo+(size_t)kt*128*DK_;
    #pragma unroll
    for(int j=0;j<2;j++){
      int v=tid+j*512; int r=v>>3, db=(v&7)*8;
      *(uint4*)(Vh+r*72+db)=*(const uint4*)(Vghi+r*64+db);
      *(uint4*)(Vl+r*72+db)=*(const uint4*)(Vglo+r*64+db);
    }
    __syncthreads();

    // scores store (fp32 = hi+lo) + rowsum accumulation (warp owns 8 rows)
    #pragma unroll
    for(int rr=0;rr<8;rr++){
      int row=warp*8+rr;
      const __nv_bfloat162* ph=(const __nv_bfloat162*)(Ph+row*136+lane*4);
      const __nv_bfloat162* pl=(const __nv_bfloat162*)(Pl+row*136+lane*4);
      float2 h0=__bfloat1622float2(ph[0]);
      float2 h1=__bfloat1622float2(ph[1]);
      float2 l0=__bfloat1622float2(pl[0]);
      float2 l1=__bfloat1622float2(pl[1]);
      float4 v;
      v.x=h0.x+l0.x; v.y=h0.y+l0.y; v.z=h1.x+l1.x; v.w=h1.y+l1.y;
      *(float4*)&scb[(size_t)row*S_+kt*128+lane*4]=v;
      rs[rr]+=v.x+v.y+v.z+v.w;
    }

    // PV: context += P @ V   (ldmatrix everywhere)
    #pragma unroll
    for(int ks=0;ks<128;ks+=16){
      uint32_t aH[2][4],aL[2][4],bH[2][2],bL[2][2];
      #pragma unroll
      for(int mi=0;mi<2;mi++){
        LDSM4(aH[mi][0],aH[mi][1],aH[mi][2],aH[mi][3], aPh[mi]+ks*2);
        LDSM4(aL[mi][0],aL[mi][1],aL[mi][2],aL[mi][3], aPl[mi]+ks*2);
      }
      LDSM4T(bH[0][0],bH[0][1],bH[1][0],bH[1][1], bVh+ks*144);
      LDSM4T(bL[0][0],bL[0][1],bL[1][0],bL[1][1], bVl+ks*144);
      #pragma unroll
      for(int mi=0;mi<2;mi++)
        #pragma unroll
        for(int ni=0;ni<2;ni++){
          mma_bf(cacc[mi][ni], aH[mi][0],aH[mi][1],aH[mi][2],aH[mi][3], bH[ni][0],bH[ni][1]);
          mma_bf(cacc[mi][ni], aH[mi][0],aH[mi][1],aH[mi][2],aH[mi][3], bL[ni][0],bL[ni][1]);
          mma_bf(cacc[mi][ni], aL[mi][0],aL[mi][1],aL[mi][2],aL[mi][3], bH[ni][0],bH[ni][1]);
        }
    }
  }

  // rowsum reduce + publish
  #pragma unroll
  for(int rr=0;rr<8;rr++){
    float v=rs[rr];
    #pragma unroll
    for(int o=16;o;o>>=1) v+=__shfl_xor_sync(0xffffffffu,v,o);
    if(lane==0){
      rsm[warp*8+rr]=v;
      g_rs[(size_t)bh*S_+qt*128+warp*8+rr]=v;
    }
  }
  __syncthreads();

  // normalized context -> g_chi/g_clo [b,s,h*64+d]  (bf16 hi/lo for out_gemm)
  size_t cbase=((size_t)(b*S_+qt*128))*D_ + h*DK_;
  #pragma unroll
  for(int mi=0;mi<2;mi++)
   #pragma unroll
   for(int ni=0;ni<2;ni++)
    #pragma unroll
    for(int e=0;e<4;e++){
      int r=wr*32+mi*16+g+((e>>1)<<3);
      int c=wc*16+ni*8+t4*2+(e&1);
      float v=cacc[mi][ni][e]/rsm[r];
      __nv_bfloat16 vh,vl; split2(v,vh,vl);
      g_chi[cbase+(size_t)r*D_+c]=vh;
      g_clo[cbase+(size_t)r*D_+c]=vl;
    }
}

// ---------------- K3: normalize scores rows ------------------------------------
__global__ __launch_bounds__(256)
void norm_scores(float* __restrict__ scores)
{
  size_t row=blockIdx.x;
  float inv=1.0f/g_rs[row];
  float4* p=(float4*)(scores+row*(size_t)S_);
  int i=threadIdx.x;
  float4 v=p[i];
  v.x*=inv; v.y*=inv; v.z*=inv; v.w*=inv;
  p[i]=v;
  float4 w=p[i+256];
  w.x*=inv; w.y*=inv; w.z*=inv; w.w*=inv;
  p[i+256]=w;
}

// ---------------- K5: LayerNorm ------------------------------------------------
__global__ __launch_bounds__(128)
void ln_kernel(const float* __restrict__ gamma, const float* __restrict__ beta,
               float* __restrict__ y)
{
  int row=blockIdx.x, tid=threadIdx.x;
  int warp=tid>>5, lane=tid&31;
  const float4 v=*(const float4*)(g_x+(size_t)row*512+tid*4);
  float s=v.x+v.y+v.z+v.w;
  #pragma unroll
  for(int o=16;o;o>>=1) s+=__shfl_xor_sync(0xffffffffu,s,o);
  __shared__ float red[4];
  if(lane==0) red[warp]=s;
  __syncthreads();
  float mean=(red[0]+red[1]+red[2]+red[3])*(1.0f/512.0f);
  float d0=v.x-mean, d1=v.y-mean, d2=v.z-mean, d3=v.w-mean;
  float q=d0*d0+d1*d1+d2*d2+d3*d3;
  #pragma unroll
  for(int o=16;o;o>>=1) q+=__shfl_xor_sync(0xffffffffu,q,o);
  __syncthreads();
  if(lane==0) red[warp]=q;
  __syncthreads();
  float var=(red[0]+red[1]+red[2]+red[3])*(1.0f/512.0f);
  float rstd=rsqrtf(var+1e-5f);
  const float4 gm=*(const float4*)(gamma+tid*4);
  const float4 bt=*(const float4*)(beta+tid*4);
  float4 o;
  o.x=d0*rstd*gm.x+bt.x;
  o.y=d1*rstd*gm.y+bt.y;
  o.z=d2*rstd*gm.z+bt.z;
  o.w=d3*rstd*gm.w+bt.w;
  *(float4*)(y+(size_t)row*512+tid*4)=o;
}

// ---------------- launch -------------------------------------------------------
extern "C" void kernel_launch(void* const* d_in, const int* in_sizes, int n_in,
                              void* d_out, int out_size)
{
  (void)in_sizes; (void)n_in; (void)out_size;
  const float* iQ=(const float*)d_in[0];
  const float* iK=(const float*)d_in[1];
  const float* iV=(const float*)d_in[2];
  const float* WQ=(const float*)d_in[3];
  const float* WK=(const float*)d_in[4];
  const float* WV=(const float*)d_in[5];
  const float* WO=(const float*)d_in[6];
  const float* gamma=(const float*)d_in[7];
  const float* beta =(const float*)d_in[8];
  float* out=(float*)d_out;
  float* y=out;
  float* scores=out+YSZ_;

  const int ATTN_SMEM = 6*(128*72)*2 + 2*(128*136)*2 + 128*4; // 180736
  cudaFuncSetAttribute(attn_kernel, cudaFuncAttributeMaxDynamicSharedMemorySize, ATTN_SMEM);
  cudaFuncSetAttribute(qkv_gemm,   cudaFuncAttributeMaxDynamicSharedMemorySize, GEMM_SMEM);
  cudaFuncSetAttribute(out_gemm,   cudaFuncAttributeMaxDynamicSharedMemorySize, GEMM_SMEM);

  split_in<<<dim3(MTOT_*D_/1024,1,3),256>>>(iQ,iK,iV);
  split_w <<<dim3(D_*D_/1024,1,4),256>>>(WQ,WK,WV,WO);

  qkv_gemm<<<dim3(4,64,3),512,GEMM_SMEM>>>();

  attn_kernel<<<dim3(16,8,4),512,ATTN_SMEM>>>(scores);

  norm_scores<<<B_*H_*S_,256>>>(scores);

  out_gemm<<<dim3(4,64,1),512,GEMM_SMEM>>>(iQ);

  ln_kernel<<<MTOT_,128>>>(gamma,beta,y);
}